// round 9
// baseline (speedup 1.0000x reference)
#include <cuda_runtime.h>

// Problem constants: B=256, T=2048, I=2, H=128, 3H=384
#define BB 256
#define TT 2048
#define HH 128
#define NTHREADS 256

__device__ int d_order[BB];

// Plain descending-length order (R2-proven best): wave 1 = 148 longest,
// wave-2 CTAs work-stolen in bid order = LPT.
__global__ void order_kernel(const int* __restrict__ lengths) {
    int i = threadIdx.x;
    int li = lengths[i];
    int rank = 0;
    #pragma unroll 8
    for (int j = 0; j < BB; j++) {
        int lj = lengths[j];
        rank += (lj > li) || (lj == li && j < i);
    }
    d_order[rank] = i;
}

// ---- packed f32x2 helpers ----
__device__ __forceinline__ unsigned long long fma2(unsigned long long a,
                                                   unsigned long long b,
                                                   unsigned long long c) {
    unsigned long long d;
    asm("fma.rn.f32x2 %0, %1, %2, %3;" : "=l"(d) : "l"(a), "l"(b), "l"(c));
    return d;
}
__device__ __forceinline__ unsigned long long add2(unsigned long long a,
                                                   unsigned long long b) {
    unsigned long long d;
    asm("add.rn.f32x2 %0, %1, %2;" : "=l"(d) : "l"(a), "l"(b));
    return d;
}
__device__ __forceinline__ unsigned long long pack2(float x, float y) {
    unsigned long long r;
    asm("mov.b64 %0, {%1, %2};" : "=l"(r) : "f"(x), "f"(y));
    return r;
}
__device__ __forceinline__ void unpack2(unsigned long long v, float& x, float& y) {
    asm("mov.b64 {%0, %1}, %2;" : "=f"(x), "=f"(y) : "l"(v));
}

__device__ __forceinline__ float tanh_fast(float v) {
    float r;
    asm("tanh.approx.f32 %0, %1;" : "=f"(r) : "f"(v));
    return r;
}

// DUO design: 256 threads, 8 warps.
//   tid 0..127  (warps 0-3): combiner. Owns r-row j (full) + n-row j LOW half
//                            (k=0..63, includes n bias). Computes the gates.
//   tid 128..255 (warps 4-7): z-producer. Owns z-row j (full) + n-row j HIGH
//                            half (k=64..127).
// Pair p = {warp p, warp p+4} (both on SMSP p) syncs via named barrier 1+p
// (64 threads). One 8-warp __syncthreads per step publishes h.
__global__ void __launch_bounds__(NTHREADS, 1)
gru_kernel(const float* __restrict__ x,        // [B, T, 2]
           const int*   __restrict__ lengths,  // [B]
           const float* __restrict__ W_ih,     // [384, 2]
           const float* __restrict__ W_hh,     // [384, 128]
           const float* __restrict__ b_ih,     // [384]
           const float* __restrict__ b_hh,     // [384]
           const float* __restrict__ head_w,   // [128]
           const float* __restrict__ head_b,   // [1]
           float*       __restrict__ out)      // [B, 1]
{
    __shared__ __align__(16) float sh_x[TT * 2 + 4];  // +pad for t+1 prefetch
    __shared__ __align__(16) float sh_h[2][HH];       // ping-pong hidden state
    __shared__ __align__(8)  float2 sh_zg[HH];        // {z', gn_hi} per j
    __shared__ float sh_red[4];

    const int tid = threadIdx.x;
    const int b = d_order[blockIdx.x];
    const int len = lengths[b];

    const int isz = tid >> 7;             // 0 = combiner(r), 1 = z-producer
    const int j = tid & 127;
    const int row = isz ? (HH + j) : j;   // own full row
    const int bar_id = 1 + ((tid >> 5) & 3);

    // --- load input prefix into shared ---
    {
        const float4* xs = reinterpret_cast<const float4*>(x + (size_t)b * (TT * 2));
        float4* xd = reinterpret_cast<float4*>(sh_x);
        int nq = (len * 2 + 3) >> 2;
        for (int q = tid; q < nq; q += NTHREADS) xd[q] = xs[q];
        if (tid < 4) sh_x[TT * 2 + tid] = 0.0f;        // prefetch pad
    }

    // --- own full row: 64 packed f32x2 registers ---
    unsigned long long w[64];
    {
        const unsigned long long* wrow =
            reinterpret_cast<const unsigned long long*>(W_hh + (size_t)row * HH);
        #pragma unroll
        for (int t = 0; t < 64; t++) w[t] = wrow[t];
    }
    // --- n-row half: 32 packed f32x2 registers ---
    unsigned long long wn[32];
    {
        const unsigned long long* wnrow = reinterpret_cast<const unsigned long long*>(
            W_hh + (size_t)(2 * HH + j) * HH + (isz ? 64 : 0));
        #pragma unroll
        for (int t = 0; t < 32; t++) wn[t] = wnrow[t];
    }
    const unsigned long long bown2 = pack2(b_hh[row], 0.0f);
    const unsigned long long bn2   = pack2(isz ? 0.0f : b_hh[2 * HH + j], 0.0f);
    const unsigned long long zero2 = pack2(0.0f, 0.0f);
    const int noff = isz ? 16 : 0;        // ull2 offset into h for n half

    // Own-row input projection consts (both rows are sigmoid gates: 0.5x).
    float pw0, pw1, pb;
    {
        float2 t2 = *reinterpret_cast<const float2*>(W_ih + (size_t)row * 2);
        pw0 = 0.5f * t2.x;
        pw1 = 0.5f * t2.y;
        pb  = 0.5f * b_ih[row];
    }
    // n input projection (combiner only; zeros on z-producer, branch-free).
    float nw0 = 0.f, nw1 = 0.f, nb = 0.f, hw = 0.f, h = 0.0f;
    if (!isz) {
        float2 t2 = *reinterpret_cast<const float2*>(W_ih + (size_t)(2 * HH + j) * 2);
        nw0 = t2.x; nw1 = t2.y;
        nb = b_ih[2 * HH + j];
        hw = head_w[j];
        sh_h[0][j] = 0.0f;
    }
    __syncthreads();

    // x-projections for t = 0.
    float2 xt0 = *reinterpret_cast<const float2*>(sh_x);
    float xp = fmaf(pw0, xt0.x, fmaf(pw1, xt0.y, pb));
    float xn = fmaf(nw0, xt0.x, fmaf(nw1, xt0.y, nb));

    int cur = 0;
    for (int t = 0; t < len; t++) {
        const ulonglong2* h2 = reinterpret_cast<const ulonglong2*>(sh_h[cur]);

        // Own full row: gown = b + W_row . h   (4 FMA2 chains, 32 LDS.128)
        unsigned long long acc0 = bown2;
        unsigned long long acc1 = zero2, acc2 = zero2, acc3 = zero2;
        #pragma unroll
        for (int k = 0; k < 16; k++) {
            ulonglong2 ha = h2[2 * k];
            ulonglong2 hb = h2[2 * k + 1];
            acc0 = fma2(w[4 * k + 0], ha.x, acc0);
            acc1 = fma2(w[4 * k + 1], ha.y, acc1);
            acc2 = fma2(w[4 * k + 2], hb.x, acc2);
            acc3 = fma2(w[4 * k + 3], hb.y, acc3);
        }
        unsigned long long s = add2(add2(acc0, acc1), add2(acc2, acc3));
        float slo, shi;
        unpack2(s, slo, shi);
        float gown = slo + shi;

        // n-row half: gn_part = [bias +] W_n[half] . h[half]  (2 chains)
        unsigned long long an0 = bn2, an1 = zero2;
        const ulonglong2* hn2 = h2 + noff;
        #pragma unroll
        for (int k = 0; k < 8; k++) {
            ulonglong2 ha = hn2[2 * k];
            ulonglong2 hb = hn2[2 * k + 1];
            an0 = fma2(wn[4 * k + 0], ha.x, an0);
            an1 = fma2(wn[4 * k + 1], ha.y, an1);
            an0 = fma2(wn[4 * k + 2], hb.x, an0);
            an1 = fma2(wn[4 * k + 3], hb.y, an1);
        }
        unsigned long long sn = add2(an0, an1);
        float nlo, nhi;
        unpack2(sn, nlo, nhi);
        float gn_part = nlo + nhi;

        if (isz) {
            // z' = 0.5*gz + xz2; publish {z', gn_hi}; prefetch next xz.
            float zp = fmaf(0.5f, gown, xp);
            sh_zg[j] = make_float2(zp, gn_part);
            asm volatile("bar.arrive %0, 64;" :: "r"(bar_id) : "memory");
            float2 xt = *reinterpret_cast<const float2*>(sh_x + 2 * (t + 1));
            xp = fmaf(pw0, xt.x, fmaf(pw1, xt.y, pb));
            __syncthreads();
        } else {
            // r_t depends only on own matvec: compute during producer wait.
            float r_t = tanh_fast(fmaf(0.5f, gown, xp));
            asm volatile("bar.sync %0, 64;" :: "r"(bar_id) : "memory");
            float2 zg = sh_zg[j];
            float gn = gn_part + zg.y;                 // full n-gate preact
            float z_t = tanh_fast(zg.x);
            float gnh = 0.5f * gn;
            float n = tanh_fast(fmaf(r_t, gnh, xn + gnh)); // tanh(xn + r*gn)
            h = 0.5f * fmaf(z_t, h - n, h + n);        // (1-z)*n + z*h
            sh_h[cur ^ 1][j] = h;
            __syncthreads();
            float2 xt = *reinterpret_cast<const float2*>(sh_x + 2 * (t + 1));
            xp = fmaf(pw0, xt.x, fmaf(pw1, xt.y, pb));
            xn = fmaf(nw0, xt.x, fmaf(nw1, xt.y, nb));
        }
        cur ^= 1;
    }

    // --- head: out[b] = sum_j h[j]*head_w[j] + head_b ---
    if (!isz) {
        float v = h * hw;
        #pragma unroll
        for (int o = 16; o > 0; o >>= 1) v += __shfl_down_sync(0xffffffffu, v, o);
        if ((tid & 31) == 0) sh_red[tid >> 5] = v;
    }
    __syncthreads();
    if (tid == 0) {
        out[b] = (sh_red[0] + sh_red[1]) + (sh_red[2] + sh_red[3]) + head_b[0];
    }
}

extern "C" void kernel_launch(void* const* d_in, const int* in_sizes, int n_in,
                              void* d_out, int out_size) {
    const float* x      = (const float*)d_in[0];
    const int*   len    = (const int*)  d_in[1];
    const float* W_ih   = (const float*)d_in[2];
    const float* W_hh   = (const float*)d_in[3];
    const float* b_ih   = (const float*)d_in[4];
    const float* b_hh   = (const float*)d_in[5];
    const float* head_w = (const float*)d_in[6];
    const float* head_b = (const float*)d_in[7];
    float* out = (float*)d_out;

    order_kernel<<<1, BB>>>(len);
    gru_kernel<<<BB, NTHREADS>>>(x, len, W_ih, W_hh, b_ih, b_hh,
                                 head_w, head_b, out);
}

// round 10
// speedup vs baseline: 1.0227x; 1.0227x over previous
#include <cuda_runtime.h>

// Problem constants: B=256, T=2048, I=2, H=128, 3H=384
#define BB 256
#define TT 2048
#define HH 128
#define NTHREADS 384

__device__ int d_order[BB];

// Plain descending-length order (R2-proven best): wave 1 = 148 longest,
// wave-2 CTAs work-stolen in bid order = LPT.
__global__ void order_kernel(const int* __restrict__ lengths) {
    int i = threadIdx.x;
    int li = lengths[i];
    int rank = 0;
    #pragma unroll 8
    for (int j = 0; j < BB; j++) {
        int lj = lengths[j];
        rank += (lj > li) || (lj == li && j < i);
    }
    d_order[rank] = i;
}

// ---- packed f32x2 helpers ----
__device__ __forceinline__ unsigned long long fma2(unsigned long long a,
                                                   unsigned long long b,
                                                   unsigned long long c) {
    unsigned long long d;
    asm("fma.rn.f32x2 %0, %1, %2, %3;" : "=l"(d) : "l"(a), "l"(b), "l"(c));
    return d;
}
__device__ __forceinline__ unsigned long long add2(unsigned long long a,
                                                   unsigned long long b) {
    unsigned long long d;
    asm("add.rn.f32x2 %0, %1, %2;" : "=l"(d) : "l"(a), "l"(b));
    return d;
}
__device__ __forceinline__ unsigned long long pack2(float x, float y) {
    unsigned long long r;
    asm("mov.b64 %0, {%1, %2};" : "=l"(r) : "f"(x), "f"(y));
    return r;
}
__device__ __forceinline__ void unpack2(unsigned long long v, float& x, float& y) {
    asm("mov.b64 {%0, %1}, %2;" : "=f"(x), "=f"(y) : "l"(v));
}

__device__ __forceinline__ float tanh_fast(float v) {
    float r;
    asm("tanh.approx.f32 %0, %1;" : "=f"(r) : "f"(v));
    return r;
}

// Roles (SWAPPED vs R8 — arbiter is hi-wid-first, so PRODUCERS get the high
// warps and drain their matvec first; the combiner consumes last):
//   tid 0..127   (warps 0-3):  r-rows (j) + combiner
//   tid 128..255 (warps 4-7):  z-rows (128+j) producer
//   tid 256..383 (warps 8-11): n-rows (256+j) producer
// Trio t = {warp t, warp t+4, warp t+8} lives on SMSP t; syncs via named
// barrier 1+t (96 thr).
//
// Overlap plan (R8-proven): combiner's r-tanh runs BEFORE its bar.sync;
// producers prefetch x-proj(t+1) between bar.arrive and __syncthreads.
// Producer-z folds its x-proj into the STS'd value; producer-n pre-reduces
// (c, d). Combiner post-bar chain: LDS.128 {c,d,z'} -> 2 MUFU -> 3 fma -> STS.
__global__ void __launch_bounds__(NTHREADS, 1)
gru_kernel(const float* __restrict__ x,        // [B, T, 2]
           const int*   __restrict__ lengths,  // [B]
           const float* __restrict__ W_ih,     // [384, 2]
           const float* __restrict__ W_hh,     // [384, 128]
           const float* __restrict__ b_ih,     // [384]
           const float* __restrict__ b_hh,     // [384]
           const float* __restrict__ head_w,   // [128]
           const float* __restrict__ head_b,   // [1]
           float*       __restrict__ out)      // [B, 1]
{
    __shared__ __align__(16) float sh_x[TT * 2 + 4];  // +pad for t+1 prefetch
    __shared__ __align__(16) float sh_h[2][HH];       // ping-pong hidden state
    __shared__ __align__(16) float4 sh_g[HH];         // {c, d, z', pad} per j
    __shared__ float sh_red[4];

    const int tid = threadIdx.x;
    const int b = d_order[blockIdx.x];
    const int len = lengths[b];

    const int role = tid >> 7;            // 0=r/combiner, 1=z, 2=n
    const int j = tid & 127;
    const int row = (role == 0) ? j : (role == 1) ? (HH + j) : (2 * HH + j);
    const int bar_id = 1 + ((tid >> 5) & 3);

    // --- load input prefix into shared ---
    {
        const float4* xs = reinterpret_cast<const float4*>(x + (size_t)b * (TT * 2));
        float4* xd = reinterpret_cast<float4*>(sh_x);
        int nq = (len * 2 + 3) >> 2;
        for (int q = tid; q < nq; q += NTHREADS) xd[q] = xs[q];
        if (tid < 4) sh_x[TT * 2 + tid] = 0.0f;        // prefetch pad
    }

    // --- W_hh row into 64 packed f32x2 registers ---
    unsigned long long w[64];
    {
        const unsigned long long* wrow =
            reinterpret_cast<const unsigned long long*>(W_hh + (size_t)row * HH);
        #pragma unroll
        for (int t = 0; t < 64; t++) w[t] = wrow[t];
    }
    const unsigned long long bhh2 = pack2(b_hh[row], 0.0f);
    const unsigned long long zero2 = pack2(0.0f, 0.0f);

    // Own-row input projection constants. sigma prescale (0.5) folded into
    // r and z rows; n row unscaled.
    const float scale = (role == 2) ? 1.0f : 0.5f;
    float pw0, pw1, pb;
    {
        float2 t2 = *reinterpret_cast<const float2*>(W_ih + (size_t)row * 2);
        pw0 = scale * t2.x;
        pw1 = scale * t2.y;
        pb  = scale * b_ih[row];
    }
    float hw = 0.f, h = 0.0f;
    if (role == 0) {
        hw = head_w[j];
        sh_h[0][j] = 0.0f;
    }
    __syncthreads();

    // x-proj for t = 0 (all threads).
    float2 xt0 = *reinterpret_cast<const float2*>(sh_x);
    float xp = fmaf(pw0, xt0.x, fmaf(pw1, xt0.y, pb));

    int cur = 0;
    for (int t = 0; t < len; t++) {
        // gh = b_hh[row] + W_hh[row] . h   (4 FMA2 chains)
        unsigned long long acc0 = bhh2;
        unsigned long long acc1 = zero2, acc2 = zero2, acc3 = zero2;
        const ulonglong2* h2 = reinterpret_cast<const ulonglong2*>(sh_h[cur]);
        #pragma unroll
        for (int k = 0; k < 16; k++) {
            ulonglong2 ha = h2[2 * k];
            ulonglong2 hb = h2[2 * k + 1];
            acc0 = fma2(w[4 * k + 0], ha.x, acc0);
            acc1 = fma2(w[4 * k + 1], ha.y, acc1);
            acc2 = fma2(w[4 * k + 2], hb.x, acc2);
            acc3 = fma2(w[4 * k + 3], hb.y, acc3);
        }
        unsigned long long s = add2(add2(acc0, acc1), add2(acc2, acc3));
        float slo, shi;
        unpack2(s, slo, shi);
        float gh = slo + shi;

        if (role != 0) {
            // Producer tails (cheap: <=2 fma + STS), then prefetch next xp
            // inside the bar2 wait window. High-wid warps -> issue priority
            // -> these finish BEFORE the combiner's matvec tail.
            if (role == 1) {
                sh_g[j].z = fmaf(0.5f, gh, xp);        // z' = 0.5*gz + xz2
            } else {
                float dnn = 0.5f * gh;                 // d = 0.5*gn
                float2 cd = make_float2(xp + dnn, dnn);
                *reinterpret_cast<float2*>(&sh_g[j]) = cd;   // {c, d}
            }
            asm volatile("bar.arrive %0, 96;" :: "r"(bar_id) : "memory");
            float2 xt = *reinterpret_cast<const float2*>(sh_x + 2 * (t + 1));
            xp = fmaf(pw0, xt.x, fmaf(pw1, xt.y, pb));
            __syncthreads();
        } else {
            // r_t depends only on own matvec; producers already arrived, so
            // bar.sync takes the fast path.
            float r_t = tanh_fast(fmaf(0.5f, gh, xp));
            asm volatile("bar.sync %0, 96;" :: "r"(bar_id) : "memory");
            float4 g = sh_g[j];                        // {c, d, z', pad}
            float z_t = tanh_fast(g.z);
            float n = tanh_fast(fmaf(r_t, g.y, g.x));  // tanh(xn + r*gn)
            h = 0.5f * fmaf(z_t, h - n, h + n);        // (1-z)*n + z*h
            sh_h[cur ^ 1][j] = h;
            __syncthreads();
            float2 xt = *reinterpret_cast<const float2*>(sh_x + 2 * (t + 1));
            xp = fmaf(pw0, xt.x, fmaf(pw1, xt.y, pb));
        }
        cur ^= 1;
    }

    // --- head: out[b] = sum_j h[j]*head_w[j] + head_b ---
    if (role == 0) {
        float v = h * hw;
        #pragma unroll
        for (int o = 16; o > 0; o >>= 1) v += __shfl_down_sync(0xffffffffu, v, o);
        if ((tid & 31) == 0) sh_red[tid >> 5] = v;
    }
    __syncthreads();
    if (tid == 0) {
        out[b] = (sh_red[0] + sh_red[1]) + (sh_red[2] + sh_red[3]) + head_b[0];
    }
}

extern "C" void kernel_launch(void* const* d_in, const int* in_sizes, int n_in,
                              void* d_out, int out_size) {
    const float* x      = (const float*)d_in[0];
    const int*   len    = (const int*)  d_in[1];
    const float* W_ih   = (const float*)d_in[2];
    const float* W_hh   = (const float*)d_in[3];
    const float* b_ih   = (const float*)d_in[4];
    const float* b_hh   = (const float*)d_in[5];
    const float* head_w = (const float*)d_in[6];
    const float* head_b = (const float*)d_in[7];
    float* out = (float*)d_out;

    order_kernel<<<1, BB>>>(len);
    gru_kernel<<<BB, NTHREADS>>>(x, len, W_ih, W_hh, b_ih, b_hh,
                                 head_w, head_b, out);
}